// round 17
// baseline (speedup 1.0000x reference)
#include <cuda_runtime.h>
#include <cuda_bf16.h>

// Zim_67430986547716 — bbox mask + Gaussian point mask.
// R17: R16 base (tied-best wall 8.672) with prologue/epilogue fat stripped:
//  - ONLY warp 0 loads boxes and writes 32+32 bbox indicator floats
//    (colf/rowf) to shared; other 224 threads skip all bbox math.
//  - Epilogue bbox mask = rowf[il] * colf[4cg..] (LDS + 4 FMUL) instead of
//    ~16 predicated ISETP/SEL slots per thread.
// Main loop / tables / shape unchanged: u16x2 tropical min, 2 pts per LDS
// pair, split accumulator chains, 1024 quadrant blocks x 256 thr, one wave.
// max_p exp(-d2/882) = exp(-(min_p d2)/882); invalid bias +30000 -> exp = 0.

#define MASK_N 64
#define NPTS   32
#define INV_STRIDE (1.0f / 16.0f)
#define INV_2SIG2  (1.0f / 882.0f)   // 2*21*21

#define DY_STRIDE 36   // uints per row (pad 4)
#define DX_STRIDE 34   // uint2 per col-group (pad 2, even => 16B-aligned pairs)

__global__ __launch_bounds__(256, 8)
void zim_masks_kernel(const float* __restrict__ boxes,
                      const float* __restrict__ pts,
                      float* __restrict__ bbox_out,
                      float* __restrict__ point_out)
{
    __shared__ __align__(16) unsigned int sdy[32 * DY_STRIDE]; // [row][p] dup (dy2+bias)
    __shared__ __align__(16) uint2        sdx[8 * DX_STRIDE];  // [cg][p] dx2 pairs (4 cols)
    __shared__ __align__(16) float colf[32];   // quadrant col in-bbox indicator
    __shared__ __align__(16) float rowf[32];   // quadrant row in-bbox indicator

    const int b      = blockIdx.x;
    const int quad   = blockIdx.y;              // 0..3
    const int i_base = (quad >> 1) << 5;        // 0 or 32
    const int j_base = (quad & 1) << 5;         // 0 or 32
    const int tid    = threadIdx.x;

    // ---- prologue: warp s (=tid>>5), lane = point. Coalesced LDG.64,
    //      conflict-free consecutive STS. Warp 0 additionally does bbox. ----
    {
        const int s    = tid >> 5;              // 0..7
        const int lane = tid & 31;              // point index
        const float2 xy = __ldg(&reinterpret_cast<const float2*>(pts)[b * NPTS + lane]);
        const int px = (int)floorf(xy.x * INV_STRIDE);
        const int py = (int)floorf(xy.y * INV_STRIDE);
        const bool valid = (px >= 0) & (py >= 0) & (px < MASK_N) & (py < MASK_N);
        const int bias = valid ? 0 : 30000;

        // dx: col group s -> cols j_base+4s .. +3, one uint2 store
        const int d0 = j_base + (s << 2) - px;
        const int d1 = d0 + 1, d2 = d0 + 2, d3 = d0 + 3;
        sdx[s * DX_STRIDE + lane] = make_uint2(
            (unsigned int)(d0 * d0) | ((unsigned int)(d1 * d1) << 16),
            (unsigned int)(d2 * d2) | ((unsigned int)(d3 * d3) << 16));

        // dy: rows 4s..4s+3, duplicated u16x2, consecutive-lane STS.32
        #pragma unroll
        for (int r = 0; r < 4; r++) {
            const int row = (s << 2) + r;
            const int d = i_base + row - py;
            const unsigned int v = (unsigned int)(d * d + bias);
            sdy[row * DY_STRIDE + lane] = v | (v << 16);
        }

        // bbox indicators: warp 0 only (uniform box, 32 rows + 32 cols)
        if (s == 0) {
            const float4 bx = __ldg(&reinterpret_cast<const float4*>(boxes)[b]);
            const int xmin_i = max((int)floorf(fminf(bx.x, bx.z) * INV_STRIDE), 0);
            const int ymin_i = max((int)floorf(fminf(bx.y, bx.w) * INV_STRIDE), 0);
            const int xmax_i = min((int)floorf(fmaxf(bx.x, bx.z) * INV_STRIDE) + 1, MASK_N);
            const int ymax_i = min((int)floorf(fmaxf(bx.y, bx.w) * INV_STRIDE) + 1, MASK_N);
            const int j = j_base + lane;
            const int i = i_base + lane;
            colf[lane] = ((j >= xmin_i) & (j < xmax_i)) ? 1.0f : 0.0f;
            rowf[lane] = ((i >= ymin_i) & (i < ymax_i)) ? 1.0f : 0.0f;
        }
    }
    __syncthreads();

    // ---- per-thread: 1 row x 4 cols; 2 points/iter, split accumulators ----
    const int il = tid >> 3;            // 0..31 local row
    const int cg = tid & 7;             // col group

    unsigned int m01a = 0xFFFFFFFFu, m23a = 0xFFFFFFFFu;
    unsigned int m01b = 0xFFFFFFFFu, m23b = 0xFFFFFFFFu;

    const unsigned int* dyb = &sdy[il * DY_STRIDE];
    const uint2*        dxb = &sdx[cg * DX_STRIDE];

    #pragma unroll
    for (int p2 = 0; p2 < NPTS / 2; p2++) {
        const uint2 dy = *reinterpret_cast<const uint2*>(dyb + 2 * p2);   // pts 2p2, 2p2+1
        const uint4 dx = *reinterpret_cast<const uint4*>(dxb + 2 * p2);   // both pts' pairs
        m01a = __viaddmin_u16x2(dy.x, dx.x, m01a);
        m23a = __viaddmin_u16x2(dy.x, dx.y, m23a);
        m01b = __viaddmin_u16x2(dy.y, dx.z, m01b);
        m23b = __viaddmin_u16x2(dy.y, dx.w, m23b);
    }
    const unsigned int m01 = __vminu2(m01a, m01b);
    const unsigned int m23 = __vminu2(m23a, m23b);

    // ---- unpack + one exp per pixel ----
    const float g0 = __expf((float)(m01 & 0xFFFFu) * -INV_2SIG2);
    const float g1 = __expf((float)(m01 >> 16)     * -INV_2SIG2);
    const float g2 = __expf((float)(m23 & 0xFFFFu) * -INV_2SIG2);
    const float g3 = __expf((float)(m23 >> 16)     * -INV_2SIG2);

    // ---- stores ----
    const int i = i_base + il;
    const int j = j_base + (cg << 2);
    const size_t base = (size_t)b * (MASK_N * MASK_N) + (size_t)i * MASK_N + j;

    *reinterpret_cast<float4*>(point_out + base) = make_float4(g0, g1, g2, g3);

    const float  rf = rowf[il];
    const float4 cf = *reinterpret_cast<const float4*>(&colf[cg << 2]);
    *reinterpret_cast<float4*>(bbox_out + base) =
        make_float4(rf * cf.x, rf * cf.y, rf * cf.z, rf * cf.w);
}

extern "C" void kernel_launch(void* const* d_in, const int* in_sizes, int n_in,
                              void* d_out, int out_size) {
    const float* boxes = (const float*)d_in[0];   // 256*4
    const float* pts   = (const float*)d_in[1];   // 256*32*2
    float* out = (float*)d_out;                   // 2 * 256*64*64
    const int B = in_sizes[0] / 4;                // 256
    float* bbox_out  = out;
    float* point_out = out + (size_t)B * MASK_N * MASK_N;
    dim3 grid(B, 4);
    zim_masks_kernel<<<grid, 256>>>(boxes, pts, bbox_out, point_out);
}